// round 2
// baseline (speedup 1.0000x reference)
#include <cuda_runtime.h>
#include <math.h>

// Problem dims (fixed by setup_inputs)
#define BB   8
#define C3   3
#define HH   512
#define WW   512
#define HP   128
#define WP   128
#define CF   256
#define SP   (HP*WP)            // 16384 spatial per plane
#define NF   (BB*CF*SP)         // 33554432 F_in elements

// Device scratch (no allocations allowed)
__device__ double g_sum;
__device__ double g_sumsq;
__device__ float  g_stats[2];          // [0] = mean*scale, [1] = scale
__device__ float  g_img_ds[BB*C3*SP];  // 4x4 avg-pooled img  (1.5 MiB)
__device__ float  g_mask01[BB*SP];     // 4x4 max-pooled binary mask
__device__ float  g_dh[BB*SP];         // distance-valued D_h
__device__ float4 g_wpack[2*CF];       // [2c]={gw0,gw1,gw2,gb}, [2c+1]={bw0,bw1,bw2,bb}

// ---------------------------------------------------------------- init: zero sums + pack weights
__global__ void init_kernel(const float* __restrict__ gw, const float* __restrict__ gB,
                            const float* __restrict__ bw, const float* __restrict__ bB) {
    int c = threadIdx.x;
    if (c == 0) { g_sum = 0.0; g_sumsq = 0.0; }
    if (c < CF) {
        g_wpack[2*c]     = make_float4(gw[3*c], gw[3*c+1], gw[3*c+2], gB[c]);
        g_wpack[2*c + 1] = make_float4(bw[3*c], bw[3*c+1], bw[3*c+2], bB[c]);
    }
}

// ---------------------------------------------------------------- global sum / sumsq of F_in
__global__ void reduce_kernel(const float4* __restrict__ F) {
    __shared__ double s_s[256];
    __shared__ double s_q[256];
    const int tid = threadIdx.x;
    long i = (long)blockIdx.x * blockDim.x + tid;
    const long stride = (long)gridDim.x * blockDim.x;
    float ps = 0.f, pq = 0.f;
    #pragma unroll 4
    for (; i < NF / 4; i += stride) {
        float4 v = F[i];
        ps += (v.x + v.y) + (v.z + v.w);
        pq += (v.x * v.x + v.y * v.y) + (v.z * v.z + v.w * v.w);
    }
    s_s[tid] = (double)ps;
    s_q[tid] = (double)pq;
    __syncthreads();
    for (int off = 128; off > 0; off >>= 1) {
        if (tid < off) {
            s_s[tid] += s_s[tid + off];
            s_q[tid] += s_q[tid + off];
        }
        __syncthreads();
    }
    if (tid == 0) {
        atomicAdd(&g_sum,   s_s[0]);
        atomicAdd(&g_sumsq, s_q[0]);
    }
}

// ---------------------------------------------------------------- finalize stats
__global__ void finalize_kernel() {
    double n = (double)NF;
    double mean = g_sum / n;
    double var = (g_sumsq - g_sum * g_sum / n) / (n - 1.0);
    double scale = 1.0 / sqrt(var * var + 1e-5);
    g_stats[0] = (float)(mean * scale);
    g_stats[1] = (float)scale;
}

// ---------------------------------------------------------------- 4x4 pools (img avg, mask max)
__global__ void pool_kernel(const float* __restrict__ img,
                            const float* __restrict__ mask) {
    const int total_img = BB * C3 * SP;   // 393216
    const int total     = total_img + BB * SP;
    int idx = blockIdx.x * blockDim.x + threadIdx.x;
    if (idx >= total) return;
    if (idx < total_img) {
        int wp = idx & 127;
        int hp = (idx >> 7) & 127;
        int ch = (idx >> 14) % 3;
        int b  = idx / (C3 * SP);
        const float* p = img + ((size_t)(b * 3 + ch) * HH + hp * 4) * WW + wp * 4;
        float s = 0.f;
        #pragma unroll
        for (int r = 0; r < 4; r++) {
            float4 v = *(const float4*)(p + (size_t)r * WW);
            s += (v.x + v.y) + (v.z + v.w);
        }
        g_img_ds[idx] = s * (1.f / 16.f);
    } else {
        int m  = idx - total_img;
        int wp = m & 127;
        int hp = (m >> 7) & 127;
        int b  = m >> 14;
        const float* p = mask + ((size_t)(b * 3) * HH + hp * 4) * WW + wp * 4;
        float mx = 0.f;
        #pragma unroll
        for (int r = 0; r < 4; r++) {
            float4 v = *(const float4*)(p + (size_t)r * WW);
            mx = fmaxf(mx, fmaxf(fmaxf(v.x, v.y), fmaxf(v.z, v.w)));
        }
        g_mask01[m] = mx;
    }
}

// ---------------------------------------------------------------- Chebyshev distance transform
// 5 iters of (3x3 dilate -> assign 2^-i to newly reached) == per-pixel:
//   d = Chebyshev distance to nearest mask==1; value = (d<=5) ? 2^-d : 0
// Random data: pooled mask is ~all ones (p(0)=2^-16) -> d=0 fast path dominates.
__global__ void dilate_kernel() {
    __shared__ float tile[26][27];   // 16x16 block + halo 5, padded
    const int tx = threadIdx.x, ty = threadIdx.y;
    const int bx = blockIdx.x * 16, by = blockIdx.y * 16;
    const int b = blockIdx.z;
    const float* mbase = &g_mask01[b * SP];

    for (int yy = ty; yy < 26; yy += 16) {
        int gy = by + yy - 5;
        for (int xx = tx; xx < 26; xx += 16) {
            int gx = bx + xx - 5;
            float v = 0.f;
            if (gy >= 0 && gy < HP && gx >= 0 && gx < WP)
                v = mbase[gy * WP + gx];
            tile[yy][xx] = v;
        }
    }
    __syncthreads();

    const int cy = ty + 5, cx = tx + 5;
    float val = 0.f;
    if (tile[cy][cx] > 0.5f) {
        val = 1.f;                        // d = 0 (dominant path)
    } else {
        int dmin = 6;
        for (int d = 1; d <= 5 && dmin == 6; d++) {
            bool hit = false;
            // top & bottom rows of the ring
            for (int dx = -d; dx <= d; dx++)
                hit |= (tile[cy - d][cx + dx] > 0.5f) | (tile[cy + d][cx + dx] > 0.5f);
            // left & right columns (excluding corners)
            for (int dy = -d + 1; dy <= d - 1; dy++)
                hit |= (tile[cy + dy][cx - d] > 0.5f) | (tile[cy + dy][cx + d] > 0.5f);
            if (hit) dmin = d;
        }
        if (dmin <= 5) val = exp2f(-(float)dmin);
    }
    g_dh[b * SP + (by + ty) * WP + (bx + tx)] = val;
}

// ---------------------------------------------------------------- fused epilogue
// Block = 256 threads, owns 1024 contiguous pixels of one batch; loads spatial
// coefficients ONCE into registers, then streams 32 channels of F -> out.
#define CHUNK_PIX 1024
#define CH_PER_BLK 32
__global__ void __launch_bounds__(256)
main_kernel(const float4* __restrict__ F, float4* __restrict__ out) {
    const int t     = threadIdx.x;
    const int chunk = blockIdx.x;              // 0..15
    const int cg    = blockIdx.y;              // 0..7
    const int b     = blockIdx.z;              // 0..7
    const int pix   = chunk * CHUNK_PIX + t * 4;

    const int sb = b * SP + pix;
    const int ib = b * 3 * SP + pix;

    float4 dh = *(const float4*)&g_dh[sb];
    float4 p0 = *(const float4*)&g_img_ds[ib];
    float4 p1 = *(const float4*)&g_img_ds[ib + SP];
    float4 p2 = *(const float4*)&g_img_ds[ib + 2 * SP];

    // Fold dh into per-pixel coefficient vectors: coef = (w0*q0 + w1*q1 + w2*q2 + bias*q3)
    float q0[4] = { p0.x * dh.x, p0.y * dh.y, p0.z * dh.z, p0.w * dh.w };
    float q1[4] = { p1.x * dh.x, p1.y * dh.y, p1.z * dh.z, p1.w * dh.w };
    float q2[4] = { p2.x * dh.x, p2.y * dh.y, p2.z * dh.z, p2.w * dh.w };
    float q3[4] = { dh.x, dh.y, dh.z, dh.w };

    const float ms = g_stats[0];   // mean*scale
    const float sc = g_stats[1];   // 1/sqrt(var^2 + 1e-5)

    const int c0 = cg * CH_PER_BLK;
    const float4* Fb = F   + (((size_t)(b * CF + c0) * SP + pix) >> 2);
    float4*       Ob = out + (((size_t)(b * CF + c0) * SP + pix) >> 2);
    const int cstride = SP >> 2;   // float4 stride per channel

    #pragma unroll 4
    for (int ci = 0; ci < CH_PER_BLK; ci++) {
        float4 gwv = __ldg(&g_wpack[2 * (c0 + ci)]);
        float4 bwv = __ldg(&g_wpack[2 * (c0 + ci) + 1]);
        float4 f = Fb[(size_t)ci * cstride];
        float4 o;
        float gc, bc, fn;

        gc = fmaf(gwv.x, q0[0], fmaf(gwv.y, q1[0], fmaf(gwv.z, q2[0], gwv.w * q3[0])));
        bc = fmaf(bwv.x, q0[0], fmaf(bwv.y, q1[0], fmaf(bwv.z, q2[0], bwv.w * q3[0])));
        fn = fmaf(f.x, sc, -ms);
        o.x = fmaf(fn, gc, bc);

        gc = fmaf(gwv.x, q0[1], fmaf(gwv.y, q1[1], fmaf(gwv.z, q2[1], gwv.w * q3[1])));
        bc = fmaf(bwv.x, q0[1], fmaf(bwv.y, q1[1], fmaf(bwv.z, q2[1], bwv.w * q3[1])));
        fn = fmaf(f.y, sc, -ms);
        o.y = fmaf(fn, gc, bc);

        gc = fmaf(gwv.x, q0[2], fmaf(gwv.y, q1[2], fmaf(gwv.z, q2[2], gwv.w * q3[2])));
        bc = fmaf(bwv.x, q0[2], fmaf(bwv.y, q1[2], fmaf(bwv.z, q2[2], bwv.w * q3[2])));
        fn = fmaf(f.z, sc, -ms);
        o.z = fmaf(fn, gc, bc);

        gc = fmaf(gwv.x, q0[3], fmaf(gwv.y, q1[3], fmaf(gwv.z, q2[3], gwv.w * q3[3])));
        bc = fmaf(bwv.x, q0[3], fmaf(bwv.y, q1[3], fmaf(bwv.z, q2[3], bwv.w * q3[3])));
        fn = fmaf(f.w, sc, -ms);
        o.w = fmaf(fn, gc, bc);

        Ob[(size_t)ci * cstride] = o;
    }
}

// ---------------------------------------------------------------- launch
extern "C" void kernel_launch(void* const* d_in, const int* in_sizes, int n_in,
                              void* d_out, int out_size) {
    const float* F_in    = (const float*)d_in[0];
    const float* img_p   = (const float*)d_in[1];
    const float* mask    = (const float*)d_in[2];
    const float* gamma_w = (const float*)d_in[3];
    const float* gamma_b = (const float*)d_in[4];
    const float* beta_w  = (const float*)d_in[5];
    const float* beta_b  = (const float*)d_in[6];
    // d_in[7] = n_ds (==2), d_in[8] = n (==2): fixed by problem shapes.
    float* out = (float*)d_out;

    init_kernel<<<1, 256>>>(gamma_w, gamma_b, beta_w, beta_b);
    reduce_kernel<<<4096, 256>>>((const float4*)F_in);

    {
        int total = BB * C3 * SP + BB * SP;
        pool_kernel<<<(total + 255) / 256, 256>>>(img_p, mask);
    }

    {
        dim3 grid(WP / 16, HP / 16, BB);
        dim3 blk(16, 16);
        dilate_kernel<<<grid, blk>>>();
    }

    finalize_kernel<<<1, 1>>>();

    {
        dim3 grid(SP / CHUNK_PIX, CF / CH_PER_BLK, BB);   // 16 x 8 x 8 = 1024 blocks
        main_kernel<<<grid, 256>>>((const float4*)F_in, (float4*)out);
    }
}

// round 3
// speedup vs baseline: 1.0450x; 1.0450x over previous
#include <cuda_runtime.h>
#include <math.h>

// Problem dims (fixed by setup_inputs)
#define BB   8
#define C3   3
#define HH   512
#define WW   512
#define HP   128
#define WP   128
#define CF   256
#define SP   (HP*WP)            // 16384 spatial per plane
#define NF   (BB*CF*SP)         // 33554432 F_in elements

// Device scratch (no allocations allowed)
__device__ double g_sum;
__device__ double g_sumsq;
__device__ float  g_stats[2];          // [0] = mean*scale, [1] = scale
__device__ float  g_img_ds[BB*C3*SP];  // 4x4 avg-pooled img  (1.5 MiB)
__device__ float  g_mask01[BB*SP];     // 4x4 max-pooled binary mask
__device__ float  g_dh[BB*SP];         // distance-valued D_h
__device__ float4 g_wpack[2*CF];       // [2c]={gw0,gw1,gw2,gb}, [2c+1]={bw0,bw1,bw2,bb}

// ---------------------------------------------------------------- pool + init (fused)
// Also zeroes the reduction accumulators and packs weights (block 0).
__global__ void pool_init_kernel(const float* __restrict__ img,
                                 const float* __restrict__ mask,
                                 const float* __restrict__ gw, const float* __restrict__ gB,
                                 const float* __restrict__ bw, const float* __restrict__ bB) {
    if (blockIdx.x == 0) {
        int c = threadIdx.x;
        if (c == 0) { g_sum = 0.0; g_sumsq = 0.0; }
        if (c < CF) {
            g_wpack[2*c]     = make_float4(gw[3*c], gw[3*c+1], gw[3*c+2], gB[c]);
            g_wpack[2*c + 1] = make_float4(bw[3*c], bw[3*c+1], bw[3*c+2], bB[c]);
        }
    }
    const int total_img = BB * C3 * SP;   // 393216
    const int total     = total_img + BB * SP;
    int idx = blockIdx.x * blockDim.x + threadIdx.x;
    if (idx >= total) return;
    if (idx < total_img) {
        int wp = idx & 127;
        int hp = (idx >> 7) & 127;
        int ch = (idx >> 14) % 3;
        int b  = idx / (C3 * SP);
        const float* p = img + ((size_t)(b * 3 + ch) * HH + hp * 4) * WW + wp * 4;
        float s = 0.f;
        #pragma unroll
        for (int r = 0; r < 4; r++) {
            float4 v = __ldcs((const float4*)(p + (size_t)r * WW));
            s += (v.x + v.y) + (v.z + v.w);
        }
        g_img_ds[idx] = s * (1.f / 16.f);
    } else {
        int m  = idx - total_img;
        int wp = m & 127;
        int hp = (m >> 7) & 127;
        int b  = m >> 14;
        const float* p = mask + ((size_t)(b * 3) * HH + hp * 4) * WW + wp * 4;
        float mx = 0.f;
        #pragma unroll
        for (int r = 0; r < 4; r++) {
            float4 v = __ldcs((const float4*)(p + (size_t)r * WW));
            mx = fmaxf(mx, fmaxf(fmaxf(v.x, v.y), fmaxf(v.z, v.w)));
        }
        g_mask01[m] = mx;
    }
}

// ---------------------------------------------------------------- global sum / sumsq of F_in
__global__ void __launch_bounds__(256)
reduce_kernel(const float4* __restrict__ F) {
    __shared__ double s_s[256];
    __shared__ double s_q[256];
    const int tid = threadIdx.x;
    // 4096 blocks x 256 threads, 8 float4 each, fully unrolled -> MLP 8
    long base = (long)blockIdx.x * blockDim.x + tid;
    const long stride = 4096L * 256L;
    float ps = 0.f, pq = 0.f;
    #pragma unroll
    for (int k = 0; k < 8; k++) {
        float4 v = __ldcs(&F[base + k * stride]);
        ps += (v.x + v.y) + (v.z + v.w);
        pq += (v.x * v.x + v.y * v.y) + (v.z * v.z + v.w * v.w);
    }
    s_s[tid] = (double)ps;
    s_q[tid] = (double)pq;
    __syncthreads();
    for (int off = 128; off > 0; off >>= 1) {
        if (tid < off) {
            s_s[tid] += s_s[tid + off];
            s_q[tid] += s_q[tid + off];
        }
        __syncthreads();
    }
    if (tid == 0) {
        atomicAdd(&g_sum,   s_s[0]);
        atomicAdd(&g_sumsq, s_q[0]);
    }
}

// ---------------------------------------------------------------- Chebyshev DT + finalize (fused)
// 5 iters of (3x3 dilate -> assign 2^-i to newly reached) == per-pixel:
//   d = Chebyshev distance to nearest mask==1; value = (d<=5) ? 2^-d : 0
// Pooled random mask is ~all ones (p(0)=2^-16): vectorized all-ones fast path.
__device__ __forceinline__ float cheb_value(const float* __restrict__ mbase, int h, int w) {
    if (mbase[h * WP + w] > 0.5f) return 1.f;
    for (int d = 1; d <= 5; d++) {
        bool hit = false;
        int y0 = h - d, y1 = h + d;
        int xlo = w - d < 0 ? 0 : w - d;
        int xhi = w + d > WP - 1 ? WP - 1 : w + d;
        if (y0 >= 0) for (int x = xlo; x <= xhi; x++) hit |= mbase[y0 * WP + x] > 0.5f;
        if (y1 < HP) for (int x = xlo; x <= xhi; x++) hit |= mbase[y1 * WP + x] > 0.5f;
        int ylo = h - d + 1 < 0 ? 0 : h - d + 1;
        int yhi = h + d - 1 > HP - 1 ? HP - 1 : h + d - 1;
        if (w - d >= 0) for (int y = ylo; y <= yhi; y++) hit |= mbase[y * WP + (w - d)] > 0.5f;
        if (w + d < WP) for (int y = ylo; y <= yhi; y++) hit |= mbase[y * WP + (w + d)] > 0.5f;
        if (hit) return exp2f(-(float)d);
    }
    return 0.f;
}

__global__ void __launch_bounds__(256)
dilate_fin_kernel() {
    int idx = blockIdx.x * blockDim.x + threadIdx.x;   // 0..32767 (one float4 each)
    if (idx == 0) {   // finalize stats (reduce completed: stream order)
        double n = (double)NF;
        double mean = g_sum / n;
        double var = (g_sumsq - g_sum * g_sum / n) / (n - 1.0);
        double scale = 1.0 / sqrt(var * var + 1e-5);
        g_stats[0] = (float)(mean * scale);
        g_stats[1] = (float)scale;
    }
    int b  = idx >> 12;
    int p4 = (idx & 4095) << 2;
    const float* mbase = &g_mask01[b * SP];
    float4 m = *(const float4*)&mbase[p4];
    float4 r;
    if (m.x > 0.5f && m.y > 0.5f && m.z > 0.5f && m.w > 0.5f) {
        r = make_float4(1.f, 1.f, 1.f, 1.f);     // dominant path
    } else {
        int h = p4 >> 7, w = p4 & 127;
        r.x = cheb_value(mbase, h, w);
        r.y = cheb_value(mbase, h, w + 1);
        r.z = cheb_value(mbase, h, w + 2);
        r.w = cheb_value(mbase, h, w + 3);
    }
    *(float4*)&g_dh[b * SP + p4] = r;
}

// ---------------------------------------------------------------- fused epilogue
// Block = 256 threads, owns 1024 contiguous pixels of one batch; loads spatial
// coefficients ONCE into registers, then streams 32 channels of F -> out.
#define CHUNK_PIX 1024
#define CH_PER_BLK 32
__global__ void __launch_bounds__(256)
main_kernel(const float4* __restrict__ F, float4* __restrict__ out) {
    const int t     = threadIdx.x;
    const int chunk = blockIdx.x;              // 0..15
    const int cg    = blockIdx.y;              // 0..7
    const int b     = blockIdx.z;              // 0..7
    const int pix   = chunk * CHUNK_PIX + t * 4;

    const int sb = b * SP + pix;
    const int ib = b * 3 * SP + pix;

    float4 dh = *(const float4*)&g_dh[sb];
    float4 p0 = *(const float4*)&g_img_ds[ib];
    float4 p1 = *(const float4*)&g_img_ds[ib + SP];
    float4 p2 = *(const float4*)&g_img_ds[ib + 2 * SP];

    // Fold dh into per-pixel coefficient vectors: coef = w0*q0 + w1*q1 + w2*q2 + bias*q3
    float q0[4] = { p0.x * dh.x, p0.y * dh.y, p0.z * dh.z, p0.w * dh.w };
    float q1[4] = { p1.x * dh.x, p1.y * dh.y, p1.z * dh.z, p1.w * dh.w };
    float q2[4] = { p2.x * dh.x, p2.y * dh.y, p2.z * dh.z, p2.w * dh.w };
    float q3[4] = { dh.x, dh.y, dh.z, dh.w };

    const float ms = g_stats[0];   // mean*scale
    const float sc = g_stats[1];   // 1/sqrt(var^2 + 1e-5)

    const int c0 = cg * CH_PER_BLK;
    const float4* Fb = F   + (((size_t)(b * CF + c0) * SP + pix) >> 2);
    float4*       Ob = out + (((size_t)(b * CF + c0) * SP + pix) >> 2);
    const int cstride = SP >> 2;   // float4 stride per channel

    #pragma unroll 8
    for (int ci = 0; ci < CH_PER_BLK; ci++) {
        float4 gwv = __ldg(&g_wpack[2 * (c0 + ci)]);
        float4 bwv = __ldg(&g_wpack[2 * (c0 + ci) + 1]);
        float4 f = __ldcs(&Fb[(size_t)ci * cstride]);
        float4 o;
        float gc, bc, fn;

        gc = fmaf(gwv.x, q0[0], fmaf(gwv.y, q1[0], fmaf(gwv.z, q2[0], gwv.w * q3[0])));
        bc = fmaf(bwv.x, q0[0], fmaf(bwv.y, q1[0], fmaf(bwv.z, q2[0], bwv.w * q3[0])));
        fn = fmaf(f.x, sc, -ms);
        o.x = fmaf(fn, gc, bc);

        gc = fmaf(gwv.x, q0[1], fmaf(gwv.y, q1[1], fmaf(gwv.z, q2[1], gwv.w * q3[1])));
        bc = fmaf(bwv.x, q0[1], fmaf(bwv.y, q1[1], fmaf(bwv.z, q2[1], bwv.w * q3[1])));
        fn = fmaf(f.y, sc, -ms);
        o.y = fmaf(fn, gc, bc);

        gc = fmaf(gwv.x, q0[2], fmaf(gwv.y, q1[2], fmaf(gwv.z, q2[2], gwv.w * q3[2])));
        bc = fmaf(bwv.x, q0[2], fmaf(bwv.y, q1[2], fmaf(bwv.z, q2[2], bwv.w * q3[2])));
        fn = fmaf(f.z, sc, -ms);
        o.z = fmaf(fn, gc, bc);

        gc = fmaf(gwv.x, q0[3], fmaf(gwv.y, q1[3], fmaf(gwv.z, q2[3], gwv.w * q3[3])));
        bc = fmaf(bwv.x, q0[3], fmaf(bwv.y, q1[3], fmaf(bwv.z, q2[3], bwv.w * q3[3])));
        fn = fmaf(f.w, sc, -ms);
        o.w = fmaf(fn, gc, bc);

        __stcs(&Ob[(size_t)ci * cstride], o);
    }
}

// ---------------------------------------------------------------- launch
extern "C" void kernel_launch(void* const* d_in, const int* in_sizes, int n_in,
                              void* d_out, int out_size) {
    const float* F_in    = (const float*)d_in[0];
    const float* img_p   = (const float*)d_in[1];
    const float* mask    = (const float*)d_in[2];
    const float* gamma_w = (const float*)d_in[3];
    const float* gamma_b = (const float*)d_in[4];
    const float* beta_w  = (const float*)d_in[5];
    const float* beta_b  = (const float*)d_in[6];
    // d_in[7] = n_ds (==2), d_in[8] = n (==2): fixed by problem shapes.
    float* out = (float*)d_out;

    {
        int total = BB * C3 * SP + BB * SP;
        pool_init_kernel<<<(total + 255) / 256, 256>>>(img_p, mask,
                                                       gamma_w, gamma_b, beta_w, beta_b);
    }

    reduce_kernel<<<4096, 256>>>((const float4*)F_in);

    dilate_fin_kernel<<<BB * SP / 4 / 256, 256>>>();

    {
        dim3 grid(SP / CHUNK_PIX, CF / CH_PER_BLK, BB);   // 16 x 8 x 8 = 1024 blocks
        main_kernel<<<grid, 256>>>((const float4*)F_in, (float4*)out);
    }
}

// round 4
// speedup vs baseline: 1.1743x; 1.1236x over previous
#include <cuda_runtime.h>
#include <math.h>

// Problem dims (fixed by setup_inputs)
#define BB   8
#define HH   512
#define WW   512
#define HP   128
#define WP   128
#define CF   256
#define SP   (HP*WP)            // 16384 spatial per plane
#define NF   (BB*CF*SP)         // 33554432 F_in elements
#define NV4  (NF/4)             // 8388608 float4s
#define GRID 512
#define TPB  256
#define PER_TH (NV4/(GRID*TPB)) // 64 float4 per thread in the reduce

// Device scratch (no allocations allowed). All slots are overwritten every
// launch; g_bar is monotonic (ticket barrier) so no reset is needed.
__device__ double g_ps[GRID];
__device__ double g_pq[GRID];
__device__ float  g_img_ds[BB*3*SP];   // 4x4 avg-pooled img (1.5 MiB)
__device__ float  g_dh[BB*SP];         // distance-valued D_h
__device__ float4 g_wpack[2*CF];       // [2c]={gw0,gw1,gw2,gb}, [2c+1]={bw..}
__device__ unsigned int g_bar;

// ---------------------------------------------------------------- grid barrier
// Monotonic ticket barrier: correct across any number of graph replays.
// Safe: grid=512 blocks, 4 blocks/SM forced via launch bounds -> 592 slots.
__device__ __forceinline__ void grid_barrier() {
    __syncthreads();
    if (threadIdx.x == 0) {
        __threadfence();
        unsigned int old = atomicAdd(&g_bar, 1u);
        unsigned int target = old - (old % GRID) + GRID;
        while (*((volatile unsigned int*)&g_bar) < target) __nanosleep(64);
        __threadfence();
    }
    __syncthreads();
}

// ---------------------------------------------------------------- on-the-fly 4x4 max-pool of raw mask
__device__ __forceinline__ float pooled_max(const float* __restrict__ mb, int h, int w) {
    const float* p = mb + (size_t)(h * 4) * WW + w * 4;
    float mx = 0.f;
    #pragma unroll
    for (int r = 0; r < 4; r++) {
        float4 v = __ldg((const float4*)(p + (size_t)r * WW));
        mx = fmaxf(mx, fmaxf(fmaxf(v.x, v.y), fmaxf(v.z, v.w)));
    }
    return mx;
}

// ---------------------------------------------------------------- the whole problem, one kernel
__global__ void __launch_bounds__(TPB, 4)
fused_kernel(const float4* __restrict__ F,
             const float*  __restrict__ img,
             const float*  __restrict__ mask,
             const float*  __restrict__ gw, const float* __restrict__ gB,
             const float*  __restrict__ bw, const float* __restrict__ bB,
             float4* __restrict__ out) {
    __shared__ double s_s[TPB];
    __shared__ double s_q[TPB];
    __shared__ float  s_stats[2];
    const int tid = threadIdx.x;
    const int bid = blockIdx.x;
    const int gt  = bid * TPB + tid;        // 0..131071

    // ---------------- Phase 1a: F_in sum / sumsq (block partials, no atomics)
    {
        float ps = 0.f, pq = 0.f;
        const long stride = (long)GRID * TPB;
        #pragma unroll 16
        for (int k = 0; k < PER_TH; k++) {
            float4 v = __ldcs(&F[(long)gt + (long)k * stride]);
            ps += (v.x + v.y) + (v.z + v.w);
            pq += (v.x * v.x + v.y * v.y) + (v.z * v.z + v.w * v.w);
        }
        s_s[tid] = (double)ps;
        s_q[tid] = (double)pq;
        __syncthreads();
        for (int off = 128; off > 0; off >>= 1) {
            if (tid < off) { s_s[tid] += s_s[tid + off]; s_q[tid] += s_q[tid + off]; }
            __syncthreads();
        }
        if (tid == 0) { g_ps[bid] = s_s[0]; g_pq[bid] = s_q[0]; }
    }

    // ---------------- Phase 1b: weight packing (first 256 global threads)
    if (gt < CF) {
        g_wpack[2*gt]     = make_float4(gw[3*gt], gw[3*gt+1], gw[3*gt+2], gB[gt]);
        g_wpack[2*gt + 1] = make_float4(bw[3*gt], bw[3*gt+1], bw[3*gt+2], bB[gt]);
    }

    // ---------------- Phase 1c: img 4x4 avg-pool (3 outputs per thread)
    for (int idx = gt; idx < BB * 3 * SP; idx += GRID * TPB) {
        int wp = idx & 127;
        int hp = (idx >> 7) & 127;
        int ch = (idx >> 14) % 3;
        int b  = idx / (3 * SP);
        const float* p = img + ((size_t)(b * 3 + ch) * HH + hp * 4) * WW + wp * 4;
        float s = 0.f;
        #pragma unroll
        for (int r = 0; r < 4; r++) {
            float4 v = __ldcs((const float4*)(p + (size_t)r * WW));
            s += (v.x + v.y) + (v.z + v.w);
        }
        g_img_ds[idx] = s * (1.f / 16.f);
    }

    // ---------------- Phase 1d: Chebyshev DT straight from the raw mask
    // 5 iters of (3x3 dilate -> 2^-i on newly reached) == per pooled pixel:
    //   d = Chebyshev dist to nearest pooled-1; value = (d<=5) ? 2^-d : 0
    // Pooled pixel = max over its 4x4 raw block, computed on the fly.
    {
        int b   = gt >> 14;
        int rem = gt & 16383;
        int h = rem >> 7, w = rem & 127;
        const float* mb = mask + (size_t)b * 3 * HH * WW;   // channel 0
        float val;
        if (pooled_max(mb, h, w) > 0.5f) {
            val = 1.f;                                       // dominant path
        } else {
            val = 0.f;
            for (int d = 1; d <= 5; d++) {
                bool hit = false;
                int y0 = h - d, y1 = h + d;
                int xlo = w - d < 0 ? 0 : w - d;
                int xhi = w + d > WP - 1 ? WP - 1 : w + d;
                if (y0 >= 0) for (int x = xlo; x <= xhi; x++) hit |= pooled_max(mb, y0, x) > 0.5f;
                if (y1 < HP) for (int x = xlo; x <= xhi; x++) hit |= pooled_max(mb, y1, x) > 0.5f;
                int ylo = h - d + 1 < 0 ? 0 : h - d + 1;
                int yhi = h + d - 1 > HP - 1 ? HP - 1 : h + d - 1;
                if (w - d >= 0) for (int y = ylo; y <= yhi; y++) hit |= pooled_max(mb, y, w - d) > 0.5f;
                if (w + d < WP) for (int y = ylo; y <= yhi; y++) hit |= pooled_max(mb, y, w + d) > 0.5f;
                if (hit) { val = exp2f(-(float)d); break; }
            }
        }
        g_dh[gt] = val;
    }

    // ================ the one grid-wide barrier ================
    grid_barrier();

    // ---------------- Phase 2: every block folds the 512 partials into stats
    {
        double ls = 0.0, lq = 0.0;
        for (int i = tid; i < GRID; i += TPB) { ls += g_ps[i]; lq += g_pq[i]; }
        s_s[tid] = ls; s_q[tid] = lq;
        __syncthreads();
        for (int off = 128; off > 0; off >>= 1) {
            if (tid < off) { s_s[tid] += s_s[tid + off]; s_q[tid] += s_q[tid + off]; }
            __syncthreads();
        }
        if (tid == 0) {
            double n = (double)NF;
            double mean = s_s[0] / n;
            double var = (s_q[0] - s_s[0] * s_s[0] / n) / (n - 1.0);
            double scale = 1.0 / sqrt(var * var + 1e-5);
            s_stats[0] = (float)(mean * scale);
            s_stats[1] = (float)scale;
        }
        __syncthreads();
    }

    const float ms = s_stats[0];
    const float sc = s_stats[1];

    // ---------------- Phase 3: fused epilogue, 2 units of (chunk,cg,b) per block
    for (int u = bid; u < 1024; u += GRID) {
        const int chunk = u & 15;
        const int cg    = (u >> 4) & 7;
        const int b     = u >> 7;
        const int pix   = chunk * 1024 + tid * 4;

        const int sb = b * SP + pix;
        const int ib = b * 3 * SP + pix;

        float4 dh = *(const float4*)&g_dh[sb];
        float4 p0 = *(const float4*)&g_img_ds[ib];
        float4 p1 = *(const float4*)&g_img_ds[ib + SP];
        float4 p2 = *(const float4*)&g_img_ds[ib + 2 * SP];

        float q0[4] = { p0.x * dh.x, p0.y * dh.y, p0.z * dh.z, p0.w * dh.w };
        float q1[4] = { p1.x * dh.x, p1.y * dh.y, p1.z * dh.z, p1.w * dh.w };
        float q2[4] = { p2.x * dh.x, p2.y * dh.y, p2.z * dh.z, p2.w * dh.w };
        float q3[4] = { dh.x, dh.y, dh.z, dh.w };

        const int c0 = cg * 32;
        const float4* Fb = F   + (((size_t)(b * CF + c0) * SP + pix) >> 2);
        float4*       Ob = out + (((size_t)(b * CF + c0) * SP + pix) >> 2);
        const int cstride = SP >> 2;

        #pragma unroll 8
        for (int ci = 0; ci < 32; ci++) {
            float4 gwv = __ldg(&g_wpack[2 * (c0 + ci)]);
            float4 bwv = __ldg(&g_wpack[2 * (c0 + ci) + 1]);
            float4 f = __ldcs(&Fb[(size_t)ci * cstride]);
            float4 o;
            float gc, bc, fn;

            gc = fmaf(gwv.x, q0[0], fmaf(gwv.y, q1[0], fmaf(gwv.z, q2[0], gwv.w * q3[0])));
            bc = fmaf(bwv.x, q0[0], fmaf(bwv.y, q1[0], fmaf(bwv.z, q2[0], bwv.w * q3[0])));
            fn = fmaf(f.x, sc, -ms);
            o.x = fmaf(fn, gc, bc);

            gc = fmaf(gwv.x, q0[1], fmaf(gwv.y, q1[1], fmaf(gwv.z, q2[1], gwv.w * q3[1])));
            bc = fmaf(bwv.x, q0[1], fmaf(bwv.y, q1[1], fmaf(bwv.z, q2[1], bwv.w * q3[1])));
            fn = fmaf(f.y, sc, -ms);
            o.y = fmaf(fn, gc, bc);

            gc = fmaf(gwv.x, q0[2], fmaf(gwv.y, q1[2], fmaf(gwv.z, q2[2], gwv.w * q3[2])));
            bc = fmaf(bwv.x, q0[2], fmaf(bwv.y, q1[2], fmaf(bwv.z, q2[2], bwv.w * q3[2])));
            fn = fmaf(f.z, sc, -ms);
            o.z = fmaf(fn, gc, bc);

            gc = fmaf(gwv.x, q0[3], fmaf(gwv.y, q1[3], fmaf(gwv.z, q2[3], gwv.w * q3[3])));
            bc = fmaf(bwv.x, q0[3], fmaf(bwv.y, q1[3], fmaf(bwv.z, q2[3], bwv.w * q3[3])));
            fn = fmaf(f.w, sc, -ms);
            o.w = fmaf(fn, gc, bc);

            __stcs(&Ob[(size_t)ci * cstride], o);
        }
    }
}

// ---------------------------------------------------------------- launch
extern "C" void kernel_launch(void* const* d_in, const int* in_sizes, int n_in,
                              void* d_out, int out_size) {
    const float* F_in    = (const float*)d_in[0];
    const float* img_p   = (const float*)d_in[1];
    const float* mask    = (const float*)d_in[2];
    const float* gamma_w = (const float*)d_in[3];
    const float* gamma_b = (const float*)d_in[4];
    const float* beta_w  = (const float*)d_in[5];
    const float* beta_b  = (const float*)d_in[6];
    // d_in[7] = n_ds (==2), d_in[8] = n (==2): fixed by problem shapes.
    float* out = (float*)d_out;

    fused_kernel<<<GRID, TPB>>>((const float4*)F_in, img_p, mask,
                                gamma_w, gamma_b, beta_w, beta_b,
                                (float4*)out);
}

// round 5
// speedup vs baseline: 1.2458x; 1.0609x over previous
#include <cuda_runtime.h>
#include <math.h>

// Problem dims (fixed by setup_inputs)
#define BB   8
#define HH   512
#define WW   512
#define HP   128
#define WP   128
#define CF   256
#define SP   (HP*WP)            // 16384 spatial per plane
#define NF   (BB*CF*SP)         // 33554432 F_in elements
#define NV4  (NF/4)             // 8388608 float4s
#define GRID 512
#define TPB  256
#define PER_TH (NV4/(GRID*TPB)) // 64 float4 per thread in the reduce

// Device scratch (no allocations allowed). All slots are overwritten every
// launch; g_bar is monotonic (ticket barrier) so no reset is needed.
__device__ double g_ps[GRID];
__device__ double g_pq[GRID];
__device__ float  g_img_ds[BB*3*SP];   // 4x4 avg-pooled img (1.5 MiB)
__device__ float  g_dh[BB*SP];         // distance-valued D_h
__device__ float4 g_wpack[2*CF];       // [2c]={gw0,gw1,gw2,gb}, [2c+1]={bw..}
__device__ unsigned int g_bar;

// ---------------------------------------------------------------- grid barrier
// Monotonic ticket barrier: correct across any number of graph replays.
// Safe: grid=512 blocks, 4 blocks/SM forced via launch bounds -> 592 slots.
__device__ __forceinline__ void grid_barrier() {
    __syncthreads();
    if (threadIdx.x == 0) {
        __threadfence();
        unsigned int old = atomicAdd(&g_bar, 1u);
        unsigned int target = old - (old % GRID) + GRID;
        while (*((volatile unsigned int*)&g_bar) < target) __nanosleep(64);
        __threadfence();
    }
    __syncthreads();
}

// ---------------------------------------------------------------- on-the-fly 4x4 max-pool of raw mask
__device__ __forceinline__ float pooled_max(const float* __restrict__ mb, int h, int w) {
    const float* p = mb + (size_t)(h * 4) * WW + w * 4;
    float mx = 0.f;
    #pragma unroll
    for (int r = 0; r < 4; r++) {
        float4 v = __ldg((const float4*)(p + (size_t)r * WW));
        mx = fmaxf(mx, fmaxf(fmaxf(v.x, v.y), fmaxf(v.z, v.w)));
    }
    return mx;
}

// ---------------------------------------------------------------- the whole problem, one kernel
__global__ void __launch_bounds__(TPB, 4)
fused_kernel(const float4* __restrict__ F,
             const float*  __restrict__ img,
             const float*  __restrict__ mask,
             const float*  __restrict__ gw, const float* __restrict__ gB,
             const float*  __restrict__ bw, const float* __restrict__ bB,
             float4* __restrict__ out) {
    __shared__ double s_s[TPB];
    __shared__ double s_q[TPB];
    __shared__ float  s_stats[2];
    const int tid = threadIdx.x;
    const int bid = blockIdx.x;
    const int gt  = bid * TPB + tid;        // 0..131071

    // ---------------- Phase 1a: weight packing (first 256 global threads)
    if (gt < CF) {
        g_wpack[2*gt]     = make_float4(gw[3*gt], gw[3*gt+1], gw[3*gt+2], gB[gt]);
        g_wpack[2*gt + 1] = make_float4(bw[3*gt], bw[3*gt+1], bw[3*gt+2], bB[gt]);
    }

    // ---------------- Phase 1b: img 4x4 avg-pool (3 outputs per thread)
    // Done BEFORE the F sweep so these reads don't evict F's tail from L2.
    for (int idx = gt; idx < BB * 3 * SP; idx += GRID * TPB) {
        int wp = idx & 127;
        int hp = (idx >> 7) & 127;
        int ch = (idx >> 14) % 3;
        int b  = idx / (3 * SP);
        const float* p = img + ((size_t)(b * 3 + ch) * HH + hp * 4) * WW + wp * 4;
        float s = 0.f;
        #pragma unroll
        for (int r = 0; r < 4; r++) {
            float4 v = __ldcs((const float4*)(p + (size_t)r * WW));
            s += (v.x + v.y) + (v.z + v.w);
        }
        g_img_ds[idx] = s * (1.f / 16.f);
    }

    // ---------------- Phase 1c: Chebyshev DT straight from the raw mask
    // 5 iters of (3x3 dilate -> 2^-i on newly reached) == per pooled pixel:
    //   d = Chebyshev dist to nearest pooled-1; value = (d<=5) ? 2^-d : 0
    {
        int b   = gt >> 14;
        int rem = gt & 16383;
        int h = rem >> 7, w = rem & 127;
        const float* mb = mask + (size_t)b * 3 * HH * WW;   // channel 0
        float val;
        if (pooled_max(mb, h, w) > 0.5f) {
            val = 1.f;                                       // dominant path
        } else {
            val = 0.f;
            for (int d = 1; d <= 5; d++) {
                bool hit = false;
                int y0 = h - d, y1 = h + d;
                int xlo = w - d < 0 ? 0 : w - d;
                int xhi = w + d > WP - 1 ? WP - 1 : w + d;
                if (y0 >= 0) for (int x = xlo; x <= xhi; x++) hit |= pooled_max(mb, y0, x) > 0.5f;
                if (y1 < HP) for (int x = xlo; x <= xhi; x++) hit |= pooled_max(mb, y1, x) > 0.5f;
                int ylo = h - d + 1 < 0 ? 0 : h - d + 1;
                int yhi = h + d - 1 > HP - 1 ? HP - 1 : h + d - 1;
                if (w - d >= 0) for (int y = ylo; y <= yhi; y++) hit |= pooled_max(mb, y, w - d) > 0.5f;
                if (w + d < WP) for (int y = ylo; y <= yhi; y++) hit |= pooled_max(mb, y, w + d) > 0.5f;
                if (hit) { val = exp2f(-(float)d); break; }
            }
        }
        g_dh[gt] = val;
    }

    // ---------------- Phase 1d: F_in sum / sumsq, DEFAULT cache policy.
    // The sweep runs front-to-back in 2 MiB waves; at the end L2 (~126MB)
    // holds the LAST ~115MB of F. Phase 3 walks F backwards to exploit it.
    {
        float ps = 0.f, pq = 0.f;
        const long stride = (long)GRID * TPB;
        #pragma unroll 16
        for (int k = 0; k < PER_TH; k++) {
            float4 v = F[(long)gt + (long)k * stride];
            ps += (v.x + v.y) + (v.z + v.w);
            pq += (v.x * v.x + v.y * v.y) + (v.z * v.z + v.w * v.w);
        }
        s_s[tid] = (double)ps;
        s_q[tid] = (double)pq;
        __syncthreads();
        for (int off = 128; off > 0; off >>= 1) {
            if (tid < off) { s_s[tid] += s_s[tid + off]; s_q[tid] += s_q[tid + off]; }
            __syncthreads();
        }
        if (tid == 0) { g_ps[bid] = s_s[0]; g_pq[bid] = s_q[0]; }
    }

    // ================ the one grid-wide barrier ================
    grid_barrier();

    // ---------------- Phase 2: every block folds the 512 partials into stats
    {
        double ls = 0.0, lq = 0.0;
        for (int i = tid; i < GRID; i += TPB) { ls += g_ps[i]; lq += g_pq[i]; }
        s_s[tid] = ls; s_q[tid] = lq;
        __syncthreads();
        for (int off = 128; off > 0; off >>= 1) {
            if (tid < off) { s_s[tid] += s_s[tid + off]; s_q[tid] += s_q[tid + off]; }
            __syncthreads();
        }
        if (tid == 0) {
            double n = (double)NF;
            double mean = s_s[0] / n;
            double var = (s_q[0] - s_s[0] * s_s[0] / n) / (n - 1.0);
            double scale = 1.0 / sqrt(var * var + 1e-5);
            s_stats[0] = (float)(mean * scale);
            s_stats[1] = (float)scale;
        }
        __syncthreads();
    }

    const float ms = s_stats[0];
    const float sc = s_stats[1];

    // ---------------- Phase 3: fused epilogue, REVERSE address order.
    // Unit index u is monotone in F address; walking u = 1023..0 re-reads F
    // newest-first so the L2-resident tail from phase 1d serves most reads.
    #pragma unroll 1
    for (int pass = 0; pass < 1024 / GRID; pass++) {
        const int u = 1023 - (pass * GRID + bid);
        const int chunk = u & 15;
        const int cg    = (u >> 4) & 7;
        const int b     = u >> 7;
        const int pix   = chunk * 1024 + tid * 4;

        const int sb = b * SP + pix;
        const int ib = b * 3 * SP + pix;

        float4 dh = *(const float4*)&g_dh[sb];
        float4 p0 = *(const float4*)&g_img_ds[ib];
        float4 p1 = *(const float4*)&g_img_ds[ib + SP];
        float4 p2 = *(const float4*)&g_img_ds[ib + 2 * SP];

        float q0[4] = { p0.x * dh.x, p0.y * dh.y, p0.z * dh.z, p0.w * dh.w };
        float q1[4] = { p1.x * dh.x, p1.y * dh.y, p1.z * dh.z, p1.w * dh.w };
        float q2[4] = { p2.x * dh.x, p2.y * dh.y, p2.z * dh.z, p2.w * dh.w };
        float q3[4] = { dh.x, dh.y, dh.z, dh.w };

        const int c0 = cg * 32;
        const float4* Fb = F   + (((size_t)(b * CF + c0) * SP + pix) >> 2);
        float4*       Ob = out + (((size_t)(b * CF + c0) * SP + pix) >> 2);
        const int cstride = SP >> 2;

        #pragma unroll 8
        for (int ci = 0; ci < 32; ci++) {
            float4 gwv = __ldg(&g_wpack[2 * (c0 + ci)]);
            float4 bwv = __ldg(&g_wpack[2 * (c0 + ci) + 1]);
            float4 f = __ldcs(&Fb[(size_t)ci * cstride]);
            float4 o;
            float gc, bc, fn;

            gc = fmaf(gwv.x, q0[0], fmaf(gwv.y, q1[0], fmaf(gwv.z, q2[0], gwv.w * q3[0])));
            bc = fmaf(bwv.x, q0[0], fmaf(bwv.y, q1[0], fmaf(bwv.z, q2[0], bwv.w * q3[0])));
            fn = fmaf(f.x, sc, -ms);
            o.x = fmaf(fn, gc, bc);

            gc = fmaf(gwv.x, q0[1], fmaf(gwv.y, q1[1], fmaf(gwv.z, q2[1], gwv.w * q3[1])));
            bc = fmaf(bwv.x, q0[1], fmaf(bwv.y, q1[1], fmaf(bwv.z, q2[1], bwv.w * q3[1])));
            fn = fmaf(f.y, sc, -ms);
            o.y = fmaf(fn, gc, bc);

            gc = fmaf(gwv.x, q0[2], fmaf(gwv.y, q1[2], fmaf(gwv.z, q2[2], gwv.w * q3[2])));
            bc = fmaf(bwv.x, q0[2], fmaf(bwv.y, q1[2], fmaf(bwv.z, q2[2], bwv.w * q3[2])));
            fn = fmaf(f.z, sc, -ms);
            o.z = fmaf(fn, gc, bc);

            gc = fmaf(gwv.x, q0[3], fmaf(gwv.y, q1[3], fmaf(gwv.z, q2[3], gwv.w * q3[3])));
            bc = fmaf(bwv.x, q0[3], fmaf(bwv.y, q1[3], fmaf(bwv.z, q2[3], bwv.w * q3[3])));
            fn = fmaf(f.w, sc, -ms);
            o.w = fmaf(fn, gc, bc);

            __stcs(&Ob[(size_t)ci * cstride], o);
        }
    }
}

// ---------------------------------------------------------------- launch
extern "C" void kernel_launch(void* const* d_in, const int* in_sizes, int n_in,
                              void* d_out, int out_size) {
    const float* F_in    = (const float*)d_in[0];
    const float* img_p   = (const float*)d_in[1];
    const float* mask    = (const float*)d_in[2];
    const float* gamma_w = (const float*)d_in[3];
    const float* gamma_b = (const float*)d_in[4];
    const float* beta_w  = (const float*)d_in[5];
    const float* beta_b  = (const float*)d_in[6];
    // d_in[7] = n_ds (==2), d_in[8] = n (==2): fixed by problem shapes.
    float* out = (float*)d_out;

    fused_kernel<<<GRID, TPB>>>((const float4*)F_in, img_p, mask,
                                gamma_w, gamma_b, beta_w, beta_b,
                                (float4*)out);
}